// round 9
// baseline (speedup 1.0000x reference)
#include <cuda_runtime.h>
#include <math.h>

// ---------------- single consolidated static scratch ----------------
// layout (float2 units):
//   A : [0        , 819200 )   8*320*320  IFFT outputs / P^T
//   B : [819200   , 1638400)   8*320*320  transpose scratch
//   C : [1638400  , 3276800)   8*320*640  640-FFT pass-1 output
//   D : [3276800  , 4915200)   8*640*320  transpose scratch
//   X : [4915200  , 8192000)   8*640*640  Xos
#define OFF_A 0
#define OFF_B 819200
#define OFF_C 1638400
#define OFF_D 3276800
#define OFF_X 4915200
#define NBUF  8192000

__device__ float2 g_buf[NBUF];
__device__ float4 g_part[200];
__device__ float4 g_norm[8];
__device__ float  g_apinv[320];

__device__ __forceinline__ int cmin(int a, int b) { return a < b ? a : b; }
__device__ __forceinline__ int cclamp(int i, int n) { int v = i < 0 ? 0 : i; return v < n ? v : n - 1; }

// ---------------- init: apodization inverse ----------------
__global__ void k_init() {
    int t = threadIdx.x;
    if (t < 320) {
        double beta = 3.141592653589793 * sqrt(19.45);  // Beatty beta, W=6, OS=2
        double f = (t - 160.0) / 640.0;
        double w6f = 3.141592653589793 * 6.0 * f;
        double arg = beta*beta - w6f*w6f;               // > 0 over this range
        double z = sqrt(arg);
        double a = sinh(z) / z;
        double a0 = sinh(beta) / beta;
        g_apinv[t] = (float)(a0 / a);
    }
}

// ---------------- mixed-radix FFT core: N = 5*M, blockDim = 5*M/2 ----------------
template<int M, int LOG2M>
__device__ __forceinline__ void fft_5m(float2* sh, int obase, float sgn) {
    const int tid = threadIdx.x;
    __syncthreads();
    const int BF = M >> 1;
    int sub = cmin(tid / BF, 4);
    int bf  = tid % BF;
    float2* s = sh + sub * M;
    #pragma unroll
    for (int st = 0; st < LOG2M; st++) {
        int mh = 1 << st;
        int j  = bf & (mh - 1);
        int base = ((bf >> st) << (st + 1)) + j;
        base = cmin(base, M - 1 - mh);
        float ang = sgn * 3.14159265358979f * (float)j / (float)mh;
        float c, sn; sincosf(ang, &sn, &c);
        float2 a = s[base];
        float2 b = s[base + mh];
        float tr = c*b.x - sn*b.y;
        float ti = c*b.y + sn*b.x;
        s[base]      = make_float2(a.x + tr, a.y + ti);
        s[base + mh] = make_float2(a.x - tr, a.y - ti);
        __syncthreads();
    }
    if (tid < M) {
        float2 z[5];
        #pragma unroll
        for (int n1 = 0; n1 < 5; n1++) z[n1] = sh[n1*M + tid];
        #pragma unroll
        for (int n1 = 1; n1 < 5; n1++) {
            float ang = sgn * 6.28318530717959f * (float)(n1 * tid) / (float)(5 * M);
            float c, sn; sincosf(ang, &sn, &c);
            float zr = c*z[n1].x - sn*z[n1].y;
            float zi = c*z[n1].y + sn*z[n1].x;
            z[n1] = make_float2(zr, zi);
        }
        const float W5R[5] = {1.f, 0.309016994374947f, -0.809016994374947f, -0.809016994374947f, 0.309016994374947f};
        const float W5I[5] = {0.f, 0.951056516295154f, 0.587785252292473f, -0.587785252292473f, -0.951056516295154f};
        #pragma unroll
        for (int k1 = 0; k1 < 5; k1++) {
            float ar = z[0].x, ai = z[0].y;
            #pragma unroll
            for (int n1 = 1; n1 < 5; n1++) {
                int q = (n1 * k1) % 5;
                float wr = W5R[q], wi = sgn * W5I[q];
                ar += wr*z[n1].x - wi*z[n1].y;
                ai += wr*z[n1].y + wi*z[n1].x;
            }
            g_buf[cclamp(obase + tid + M*k1, NBUF)] = make_float2(ar, ai);
        }
    }
}

// ---------------- phase 1: 320-point inverse FFTs ----------------
__global__ __launch_bounds__(160) void k_ifft320_a(const float* __restrict__ kr,
                                                   const float* __restrict__ ki, int kel) {
    __shared__ float2 sh[320];
    int b = blockIdx.y, u = blockIdx.x;
    int rowbase = (b*320 + u)*320;
    for (int e = threadIdx.x; e < 320; e += 160) {
        int n1 = e >> 6, j = e & 63;
        int src = n1 + 5 * (int)(__brev((unsigned)j) >> 26);
        int idx = cclamp(rowbase + src, kel);
        sh[e] = make_float2(kr[idx], ki[idx]);
    }
    fft_5m<64,6>(sh, OFF_A + rowbase, 1.f);
}

__global__ __launch_bounds__(160) void k_ifft320_b() {
    __shared__ float2 sh[320];
    int b = blockIdx.y, y = blockIdx.x;
    int rowbase = (b*320 + y)*320;
    for (int e = threadIdx.x; e < 320; e += 160) {
        int n1 = e >> 6, j = e & 63;
        sh[e] = g_buf[cclamp(OFF_B + rowbase + n1 + 5 * (int)(__brev((unsigned)j) >> 26), NBUF)];
    }
    fft_5m<64,6>(sh, OFF_A + rowbase, 1.f);
}

// ---------------- transposes ----------------
__global__ void k_trans320() {
    __shared__ float2 tile[32][33];
    int b = blockIdx.z;
    int base = b*320*320;
    int c = blockIdx.x*32 + threadIdx.x;
    int r0 = blockIdx.y*32;
    #pragma unroll
    for (int i = threadIdx.y; i < 32; i += 8)
        tile[i][threadIdx.x] = g_buf[cclamp(OFF_A + base + (r0 + i)*320 + c, NBUF)];
    __syncthreads();
    int oc = r0 + threadIdx.x;
    int or0 = blockIdx.x*32;
    #pragma unroll
    for (int i = threadIdx.y; i < 32; i += 8)
        g_buf[cclamp(OFF_B + base + (or0 + i)*320 + oc, NBUF)] = tile[threadIdx.x][i];
}

__global__ void k_trans640() {
    __shared__ float2 tile[32][33];
    int b = blockIdx.z;
    int c = blockIdx.x*32 + threadIdx.x;
    int r0 = blockIdx.y*32;
    #pragma unroll
    for (int i = threadIdx.y; i < 32; i += 8)
        tile[i][threadIdx.x] = g_buf[cclamp(OFF_C + b*320*640 + (r0 + i)*640 + c, NBUF)];
    __syncthreads();
    int oc = r0 + threadIdx.x;
    int or0 = blockIdx.x*32;
    #pragma unroll
    for (int i = threadIdx.y; i < 32; i += 8)
        g_buf[cclamp(OFF_D + b*640*320 + (or0 + i)*320 + oc, NBUF)] = tile[threadIdx.x][i];
}

// ---------------- two-stage reduction for mean/std ----------------
__global__ __launch_bounds__(256) void k_reduce() {
    __shared__ float4 warpsum[8];
    int b = blockIdx.y;
    float sR = 0.f, sR2 = 0.f, sI = 0.f, sI2 = 0.f;
    int base = blockIdx.x*4096;
    #pragma unroll
    for (int i = 0; i < 16; i++) {
        int idx = base + threadIdx.x + i*256;
        float2 v = g_buf[cclamp(OFF_A + b*102400 + idx, NBUF)];
        int y = idx / 320;
        int x = idx - y*320;
        float sg = ((x + y) & 1) ? -1.f : 1.f;
        sR  += sg * v.x;
        sR2 += v.x * v.x;
        sI  += sg * v.y;
        sI2 += v.y * v.y;
    }
    #pragma unroll
    for (int o = 16; o > 0; o >>= 1) {
        sR  += __shfl_down_sync(0xffffffff, sR,  o);
        sR2 += __shfl_down_sync(0xffffffff, sR2, o);
        sI  += __shfl_down_sync(0xffffffff, sI,  o);
        sI2 += __shfl_down_sync(0xffffffff, sI2, o);
    }
    int lane = threadIdx.x & 31, wid = threadIdx.x >> 5;
    if (lane == 0) warpsum[wid] = make_float4(sR, sR2, sI, sI2);
    __syncthreads();
    if (threadIdx.x == 0) {
        float4 t = warpsum[0];
        #pragma unroll
        for (int w = 1; w < 8; w++) {
            float4 u = warpsum[w];
            t.x += u.x; t.y += u.y; t.z += u.z; t.w += u.w;
        }
        g_part[cclamp(b*25 + blockIdx.x, 200)] = t;
    }
}

__global__ void k_fin() {
    int b = threadIdx.x;
    if (b >= 8) return;
    double sR = 0, sR2 = 0, sI = 0, sI2 = 0;
    for (int j = 0; j < 25; j++) {
        float4 t = g_part[b*25 + j];
        sR += t.x; sR2 += t.y; sI += t.z; sI2 += t.w;
    }
    const double N = 102400.0;
    double sv_r = sR / 320.0;                 // sum image_r   (image = s*P/320)
    double sq_r = sR2 / 102400.0;             // sum image_r^2 (/320^2)
    double sv_i = sI / 320.0;
    double sq_i = sI2 / 102400.0;
    double mR = sv_r / N;
    double vR = (sq_r - sv_r*sv_r/N) / (N - 1.0);
    double mI = sv_i / N;
    double vI = (sq_i - sv_i*sv_i/N) / (N - 1.0);
    g_norm[b] = make_float4((float)mR, (float)(1.0/sqrt(vR)),
                            (float)mI, (float)(1.0/sqrt(vI)));
}

// ---------------- phase 2: 640-point forward FFTs (corner input) ----------------
__global__ __launch_bounds__(320) void k_fft640_a() {
    __shared__ float2 sh[640];
    int b = blockIdx.y, y = blockIdx.x;
    float4 nm = g_norm[cmin(b,7)];
    int yy = (y < 160) ? y + 160 : y - 160;
    float apy = g_apinv[cclamp(y,320)];
    for (int e = threadIdx.x; e < 640; e += 320) {
        int n1 = e >> 7, j = e & 127;
        int src = n1 + 5 * (int)(__brev((unsigned)j) >> 25);
        float2 v = make_float2(0.f, 0.f);
        if (src < 320) {
            int x = src;
            int xx = (x < 160) ? x + 160 : x - 160;
            float2 p = g_buf[cclamp(OFF_A + (b*320 + yy)*320 + xx, NBUF)];
            float c = ((x + y) & 1) ? -0.003125f : 0.003125f;  // s(x,y)/320
            float re = (c*p.x - nm.x) * nm.y;
            float im = (c*p.y - nm.z) * nm.w;
            float sc = apy * g_apinv[cclamp(x,320)];
            v = make_float2(re*sc, im*sc);
        }
        sh[e] = v;
    }
    fft_5m<128,7>(sh, OFF_C + (b*320 + y)*640, -1.f);
}

__global__ __launch_bounds__(320) void k_fft640_b() {
    __shared__ float2 sh[640];
    int b = blockIdx.y, u = blockIdx.x;
    for (int e = threadIdx.x; e < 640; e += 320) {
        int n1 = e >> 7, j = e & 127;
        int src = n1 + 5 * (int)(__brev((unsigned)j) >> 25);
        sh[e] = (src < 320) ? g_buf[cclamp(OFF_D + b*640*320 + u*320 + src, NBUF)]
                            : make_float2(0.f, 0.f);
    }
    fft_5m<128,7>(sh, OFF_X + (b*640 + u)*640, -1.f);
}

// ---------------- Kaiser-Bessel i0 and gather ----------------
__device__ __forceinline__ float i0f(float x) {
    if (x < 3.75f) {
        float t = x * (1.0f/3.75f); float t2 = t*t;
        return 1.0f + t2*(3.5156229f + t2*(3.0899424f + t2*(1.2067492f +
               t2*(0.2659732f + t2*(0.0360768f + t2*0.0045813f)))));
    } else {
        float t = 3.75f / x;
        float p = 0.39894228f + t*(0.01328592f + t*(0.00225319f + t*(-0.00157565f +
                  t*(0.00916281f + t*(-0.02057706f + t*(0.02635537f +
                  t*(-0.01647633f + t*0.00392377f)))))));
        return expf(x) * rsqrtf(x) * p;
    }
}

// Output: REAL PART only — d_out is 4,096,000 float32 (16 MB), matching the
// harness's float32 materialization of the complex reference.
__global__ __launch_bounds__(256) void k_gather(const float* __restrict__ tkx,
                                                const float* __restrict__ tky,
                                                float* __restrict__ out,
                                                int tel) {
    int p = blockIdx.x*256 + threadIdx.x;
    if (p >= 512000) return;
    const float beta = (float)(3.141592653589793 * sqrt(19.45));
    const float inv_i0b = 1.0f / i0f(beta);
    int tp = cclamp(p, tel);
    float gx = tkx[tp] * 2.0f;   // G/H = 2
    float gy = tky[tp] * 2.0f;
    if (!(gx > -321.f && gx < 321.f)) gx = 0.f;
    if (!(gy > -321.f && gy < 321.f)) gy = 0.f;
    int ix0 = (int)floorf(gx) - 2;
    int iy0 = (int)floorf(gy) - 2;
    float axr[6], axi[6], ayr[6], ayi[6];
    int ixm[6], iym[6];
    #pragma unroll
    for (int j = 0; j < 6; j++) {
        {   // x taps: weight * i^{(ix0+j)}  (corner-shift phase fold)
            float d = gx - (float)(ix0 + j);
            float arg = fmaxf(1.0f - d*d*(1.0f/9.0f), 0.0f);
            float w = i0f(beta * sqrtf(arg)) * inv_i0b;
            int q = (ix0 + j + 1024) & 3;
            axr[j] = (q == 0) ? w : ((q == 2) ? -w : 0.f);
            axi[j] = (q == 1) ? w : ((q == 3) ? -w : 0.f);
            int v = ix0 + j; if (v < 0) v += 640;
            ixm[j] = cclamp(v, 640);
        }
        {
            float d = gy - (float)(iy0 + j);
            float arg = fmaxf(1.0f - d*d*(1.0f/9.0f), 0.0f);
            float w = i0f(beta * sqrtf(arg)) * inv_i0b;
            int q = (iy0 + j + 1024) & 3;
            ayr[j] = (q == 0) ? w : ((q == 2) ? -w : 0.f);
            ayi[j] = (q == 1) ? w : ((q == 3) ? -w : 0.f);
            int v = iy0 + j; if (v < 0) v += 640;
            iym[j] = cclamp(v, 640);
        }
    }
    #pragma unroll 1
    for (int b = 0; b < 8; b++) {
        float accr = 0.f;
        #pragma unroll
        for (int jx = 0; jx < 6; jx++) {
            int rowb = OFF_X + b*409600 + ixm[jx]*640;
            float tr = 0.f, ti = 0.f;
            #pragma unroll
            for (int jy = 0; jy < 6; jy++) {
                float2 v = g_buf[cclamp(rowb + iym[jy], NBUF)];
                tr += ayr[jy]*v.x - ayi[jy]*v.y;
                ti += ayr[jy]*v.y + ayi[jy]*v.x;
            }
            accr += axr[jx]*tr - axi[jx]*ti;   // Re of (ax * t)
        }
        out[b*512000 + p] = accr;
    }
}

// ---------------- host launcher ----------------
static inline int elems_of(int s, int expected) {
    if (s == expected) return s;
    if (s / 4 == expected) return expected;
    return s;
}

extern "C" void kernel_launch(void* const* d_in, const int* in_sizes, int n_in,
                              void* d_out, int out_size) {
    const float *kr = 0, *ki = 0, *tkx = 0, *tky = 0;
    int kel = 0, tel = 0;
    for (int i = 0; i < n_in; i++) {
        int s = in_sizes[i];
        if (s == 819200 || s == 3276800) {
            if (!kr) { kr = (const float*)d_in[i]; kel = elems_of(s, 819200); }
            else if (!ki) ki = (const float*)d_in[i];
        } else if (s == 512000 || s == 2048000) {
            if (!tkx) { tkx = (const float*)d_in[i]; tel = elems_of(s, 512000); }
            else if (!tky) tky = (const float*)d_in[i];
        }
    }
    if ((!kr || !ki || !tkx || !tky) && n_in >= 4) {
        kr  = (const float*)d_in[0]; kel = in_sizes[0] > 0 ? in_sizes[0] : 1;
        ki  = (const float*)d_in[1];
        tkx = (const float*)d_in[2]; tel = in_sizes[2] > 0 ? in_sizes[2] : 1;
        tky = (const float*)d_in[3];
        if (kel > 819200) kel = 819200;
        if (tel > 512000) tel = 512000;
    }
    if (!kr || !ki || !tkx || !tky || !d_out || kel <= 0 || tel <= 0) return;
    float* out = (float*)d_out;

    k_init<<<1, 512>>>();
    k_ifft320_a<<<dim3(320, 8), 160>>>(kr, ki, kel);     // IFFT along v
    k_trans320<<<dim3(10, 10, 8), dim3(32, 8)>>>();
    k_ifft320_b<<<dim3(320, 8), 160>>>();                // IFFT along u -> P^T
    k_reduce<<<dim3(25, 8), 256>>>();
    k_fin<<<1, 32>>>();
    k_fft640_a<<<dim3(320, 8), 320>>>();                 // FFT along x (normalized+apodized corner)
    k_trans640<<<dim3(20, 10, 8), dim3(32, 8)>>>();
    k_fft640_b<<<dim3(640, 8), 320>>>();                 // FFT along y -> Xos
    k_gather<<<2000, 256>>>(tkx, tky, out, tel);
}

// round 10
// speedup vs baseline: 1.0278x; 1.0278x over previous
#include <cuda_runtime.h>
#include <math.h>

// ---------------- single consolidated static scratch ----------------
// layout (float2 units):
//   A : [0        , 819200 )   8*320*320  IFFT outputs / P^T
//   B : [819200   , 1638400)   8*320*320  transpose scratch
//   C : [1638400  , 3276800)   8*320*640  640-FFT pass-1 output
//   D : [3276800  , 4915200)   8*640*320  transpose scratch
//   X : [4915200  , 8192000)   8*640*640  Xos
#define OFF_A 0
#define OFF_B 819200
#define OFF_C 1638400
#define OFF_D 3276800
#define OFF_X 4915200
#define NBUF  8192000

__device__ float2 g_buf[NBUF];
__device__ float4 g_part[200];
__device__ float4 g_norm[8];
__device__ float  g_apinv[320];
__device__ float2 g_tw[640];     // W640^m = (cos(2pi m/640), -sin(2pi m/640))  [forward]

// ---------------- init: twiddle table + apodization inverse ----------------
__global__ void k_init() {
    int t = threadIdx.x;
    if (t < 640) {
        double a = 2.0 * 3.141592653589793 * (double)t / 640.0;
        double c, s; sincos(a, &s, &c);
        g_tw[t] = make_float2((float)c, (float)(-s));
    }
    if (t < 320) {
        double beta = 3.141592653589793 * sqrt(19.45);  // Beatty beta, W=6, OS=2
        double f = (t - 160.0) / 640.0;
        double w6f = 3.141592653589793 * 6.0 * f;
        double arg = beta*beta - w6f*w6f;               // > 0 over this range
        double z = sqrt(arg);
        double a = sinh(z) / z;
        double a0 = sinh(beta) / beta;
        g_apinv[t] = (float)(a0 / a);
    }
}

// ---------------- mixed-radix FFT core: N = 5*M, blockDim = 5*M/2 ----------------
// CONJ=false: forward (e^{-i...}); CONJ=true: inverse (e^{+i...}).
// NSC: table stride = 640/(5*M).
template<int M, int LOG2M, int NSC, bool CONJ>
__device__ __forceinline__ void fft_5m(float2* sh, int obase) {
    const int tid = threadIdx.x;
    __syncthreads();
    const int BF = M >> 1;
    int sub = tid / BF;
    int bf  = tid - sub * BF;
    float2* s = sh + sub * M;
    #pragma unroll
    for (int st = 0; st < LOG2M; st++) {
        int mh = 1 << st;
        int j  = bf & (mh - 1);
        int base = ((bf >> st) << (st + 1)) + j;
        float2 w = __ldg(&g_tw[j * (320 >> st)]);
        float wy = CONJ ? -w.y : w.y;
        float2 a = s[base];
        float2 b = s[base + mh];
        float tr = w.x*b.x - wy*b.y;
        float ti = w.x*b.y + wy*b.x;
        s[base]      = make_float2(a.x + tr, a.y + ti);
        s[base + mh] = make_float2(a.x - tr, a.y - ti);
        __syncthreads();
    }
    if (tid < M) {
        float2 z[5];
        #pragma unroll
        for (int n1 = 0; n1 < 5; n1++) z[n1] = sh[n1*M + tid];
        #pragma unroll
        for (int n1 = 1; n1 < 5; n1++) {
            float2 w = __ldg(&g_tw[n1 * tid * NSC]);   // n1*tid*NSC < 640 always
            float wy = CONJ ? -w.y : w.y;
            float zr = w.x*z[n1].x - wy*z[n1].y;
            float zi = w.x*z[n1].y + wy*z[n1].x;
            z[n1] = make_float2(zr, zi);
        }
        const float W5R[5] = {1.f, 0.309016994374947f, -0.809016994374947f, -0.809016994374947f, 0.309016994374947f};
        const float W5I[5] = {0.f, 0.951056516295154f, 0.587785252292473f, -0.587785252292473f, -0.951056516295154f};
        const float s5 = CONJ ? 1.f : -1.f;
        #pragma unroll
        for (int k1 = 0; k1 < 5; k1++) {
            float ar = z[0].x, ai = z[0].y;
            #pragma unroll
            for (int n1 = 1; n1 < 5; n1++) {
                int q = (n1 * k1) % 5;
                float wr = W5R[q], wi = s5 * W5I[q];
                ar += wr*z[n1].x - wi*z[n1].y;
                ai += wr*z[n1].y + wi*z[n1].x;
            }
            g_buf[obase + tid + M*k1] = make_float2(ar, ai);
        }
    }
}

// ---------------- phase 1: 320-point inverse FFTs ----------------
__global__ __launch_bounds__(160) void k_ifft320_a(const float* __restrict__ kr,
                                                   const float* __restrict__ ki) {
    __shared__ float2 sh[320];
    int b = blockIdx.y, u = blockIdx.x;
    int rowbase = (b*320 + u)*320;
    for (int e = threadIdx.x; e < 320; e += 160) {
        int n1 = e >> 6, j = e & 63;
        int src = n1 + 5 * (int)(__brev((unsigned)j) >> 26);
        sh[e] = make_float2(__ldg(&kr[rowbase + src]), __ldg(&ki[rowbase + src]));
    }
    fft_5m<64,6,2,true>(sh, OFF_A + rowbase);
}

__global__ __launch_bounds__(160) void k_ifft320_b() {
    __shared__ float2 sh[320];
    int b = blockIdx.y, y = blockIdx.x;
    int rowbase = (b*320 + y)*320;
    for (int e = threadIdx.x; e < 320; e += 160) {
        int n1 = e >> 6, j = e & 63;
        sh[e] = g_buf[OFF_B + rowbase + n1 + 5 * (int)(__brev((unsigned)j) >> 26)];
    }
    fft_5m<64,6,2,true>(sh, OFF_A + rowbase);
}

// ---------------- transposes ----------------
__global__ void k_trans320() {
    __shared__ float2 tile[32][33];
    int b = blockIdx.z;
    int base = b*320*320;
    int c = blockIdx.x*32 + threadIdx.x;
    int r0 = blockIdx.y*32;
    #pragma unroll
    for (int i = threadIdx.y; i < 32; i += 8)
        tile[i][threadIdx.x] = g_buf[OFF_A + base + (r0 + i)*320 + c];
    __syncthreads();
    int oc = r0 + threadIdx.x;
    int or0 = blockIdx.x*32;
    #pragma unroll
    for (int i = threadIdx.y; i < 32; i += 8)
        g_buf[OFF_B + base + (or0 + i)*320 + oc] = tile[threadIdx.x][i];
}

__global__ void k_trans640() {
    __shared__ float2 tile[32][33];
    int b = blockIdx.z;
    int c = blockIdx.x*32 + threadIdx.x;
    int r0 = blockIdx.y*32;
    #pragma unroll
    for (int i = threadIdx.y; i < 32; i += 8)
        tile[i][threadIdx.x] = g_buf[OFF_C + b*320*640 + (r0 + i)*640 + c];
    __syncthreads();
    int oc = r0 + threadIdx.x;
    int or0 = blockIdx.x*32;
    #pragma unroll
    for (int i = threadIdx.y; i < 32; i += 8)
        g_buf[OFF_D + b*640*320 + (or0 + i)*320 + oc] = tile[threadIdx.x][i];
}

// ---------------- two-stage reduction for mean/std ----------------
__global__ __launch_bounds__(256) void k_reduce() {
    __shared__ float4 warpsum[8];
    int b = blockIdx.y;
    float sR = 0.f, sR2 = 0.f, sI = 0.f, sI2 = 0.f;
    int base = blockIdx.x*4096;
    #pragma unroll
    for (int i = 0; i < 16; i++) {
        int idx = base + threadIdx.x + i*256;
        float2 v = g_buf[OFF_A + b*102400 + idx];
        int y = idx / 320;
        int x = idx - y*320;
        float sg = ((x + y) & 1) ? -1.f : 1.f;
        sR  += sg * v.x;
        sR2 += v.x * v.x;
        sI  += sg * v.y;
        sI2 += v.y * v.y;
    }
    #pragma unroll
    for (int o = 16; o > 0; o >>= 1) {
        sR  += __shfl_down_sync(0xffffffff, sR,  o);
        sR2 += __shfl_down_sync(0xffffffff, sR2, o);
        sI  += __shfl_down_sync(0xffffffff, sI,  o);
        sI2 += __shfl_down_sync(0xffffffff, sI2, o);
    }
    int lane = threadIdx.x & 31, wid = threadIdx.x >> 5;
    if (lane == 0) warpsum[wid] = make_float4(sR, sR2, sI, sI2);
    __syncthreads();
    if (threadIdx.x == 0) {
        float4 t = warpsum[0];
        #pragma unroll
        for (int w = 1; w < 8; w++) {
            float4 u = warpsum[w];
            t.x += u.x; t.y += u.y; t.z += u.z; t.w += u.w;
        }
        g_part[b*25 + blockIdx.x] = t;
    }
}

__global__ void k_fin() {
    int b = threadIdx.x;
    if (b >= 8) return;
    double sR = 0, sR2 = 0, sI = 0, sI2 = 0;
    for (int j = 0; j < 25; j++) {
        float4 t = g_part[b*25 + j];
        sR += t.x; sR2 += t.y; sI += t.z; sI2 += t.w;
    }
    const double N = 102400.0;
    double sv_r = sR / 320.0;
    double sq_r = sR2 / 102400.0;
    double sv_i = sI / 320.0;
    double sq_i = sI2 / 102400.0;
    double mR = sv_r / N;
    double vR = (sq_r - sv_r*sv_r/N) / (N - 1.0);
    double mI = sv_i / N;
    double vI = (sq_i - sv_i*sv_i/N) / (N - 1.0);
    g_norm[b] = make_float4((float)mR, (float)(1.0/sqrt(vR)),
                            (float)mI, (float)(1.0/sqrt(vI)));
}

// ---------------- phase 2: 640-point forward FFTs (corner input) ----------------
__global__ __launch_bounds__(320) void k_fft640_a() {
    __shared__ float2 sh[640];
    int b = blockIdx.y, y = blockIdx.x;
    float4 nm = g_norm[b];
    int yy = (y < 160) ? y + 160 : y - 160;
    float apy = g_apinv[y];
    for (int e = threadIdx.x; e < 640; e += 320) {
        int n1 = e >> 7, j = e & 127;
        int src = n1 + 5 * (int)(__brev((unsigned)j) >> 25);
        float2 v = make_float2(0.f, 0.f);
        if (src < 320) {
            int x = src;
            int xx = (x < 160) ? x + 160 : x - 160;
            float2 p = g_buf[OFF_A + (b*320 + yy)*320 + xx];
            float c = ((x + y) & 1) ? -0.003125f : 0.003125f;  // s(x,y)/320
            float re = (c*p.x - nm.x) * nm.y;
            float im = (c*p.y - nm.z) * nm.w;
            float sc = apy * g_apinv[x];
            v = make_float2(re*sc, im*sc);
        }
        sh[e] = v;
    }
    fft_5m<128,7,1,false>(sh, OFF_C + (b*320 + y)*640);
}

__global__ __launch_bounds__(320) void k_fft640_b() {
    __shared__ float2 sh[640];
    int b = blockIdx.y, u = blockIdx.x;
    for (int e = threadIdx.x; e < 640; e += 320) {
        int n1 = e >> 7, j = e & 127;
        int src = n1 + 5 * (int)(__brev((unsigned)j) >> 25);
        sh[e] = (src < 320) ? g_buf[OFF_D + b*640*320 + u*320 + src]
                            : make_float2(0.f, 0.f);
    }
    fft_5m<128,7,1,false>(sh, OFF_X + (b*640 + u)*640);
}

// ---------------- Kaiser-Bessel i0 (fast exp) and gather ----------------
__device__ __forceinline__ float i0f(float x) {
    if (x < 3.75f) {
        float t = x * (1.0f/3.75f); float t2 = t*t;
        return 1.0f + t2*(3.5156229f + t2*(3.0899424f + t2*(1.2067492f +
               t2*(0.2659732f + t2*(0.0360768f + t2*0.0045813f)))));
    } else {
        float t = 3.75f / x;
        float p = 0.39894228f + t*(0.01328592f + t*(0.00225319f + t*(-0.00157565f +
                  t*(0.00916281f + t*(-0.02057706f + t*(0.02635537f +
                  t*(-0.01647633f + t*0.00392377f)))))));
        return __expf(x) * rsqrtf(x) * p;
    }
}

// Output: REAL PART only — d_out is 4,096,000 float32 (16 MB).
__global__ __launch_bounds__(256) void k_gather(const float* __restrict__ tkx,
                                                const float* __restrict__ tky,
                                                float* __restrict__ out) {
    int p = blockIdx.x*256 + threadIdx.x;
    if (p >= 512000) return;
    const float beta = (float)(3.141592653589793 * sqrt(19.45));
    const float inv_i0b = 1.0f / i0f(beta);
    float gx = __ldg(&tkx[p]) * 2.0f;   // G/H = 2
    float gy = __ldg(&tky[p]) * 2.0f;
    if (!(gx > -321.f && gx < 321.f)) gx = 0.f;   // NaN-safe
    if (!(gy > -321.f && gy < 321.f)) gy = 0.f;
    int ix0 = (int)floorf(gx) - 2;
    int iy0 = (int)floorf(gy) - 2;
    float axr[6], axi[6], ayr[6], ayi[6];
    int ixm[6], iym[6];
    #pragma unroll
    for (int j = 0; j < 6; j++) {
        {   // x taps: weight * i^{(ix0+j)}  (corner-shift phase fold)
            float d = gx - (float)(ix0 + j);
            float arg = fmaxf(1.0f - d*d*(1.0f/9.0f), 0.0f);
            float w = i0f(beta * sqrtf(arg)) * inv_i0b;
            int q = (ix0 + j + 1024) & 3;
            axr[j] = (q == 0) ? w : ((q == 2) ? -w : 0.f);
            axi[j] = (q == 1) ? w : ((q == 3) ? -w : 0.f);
            int v = ix0 + j; if (v < 0) v += 640;
            ixm[j] = v;
        }
        {
            float d = gy - (float)(iy0 + j);
            float arg = fmaxf(1.0f - d*d*(1.0f/9.0f), 0.0f);
            float w = i0f(beta * sqrtf(arg)) * inv_i0b;
            int q = (iy0 + j + 1024) & 3;
            ayr[j] = (q == 0) ? w : ((q == 2) ? -w : 0.f);
            ayi[j] = (q == 1) ? w : ((q == 3) ? -w : 0.f);
            int v = iy0 + j; if (v < 0) v += 640;
            iym[j] = v;
        }
    }
    #pragma unroll 1
    for (int b = 0; b < 8; b++) {
        float accr = 0.f;
        #pragma unroll
        for (int jx = 0; jx < 6; jx++) {
            int rowb = OFF_X + b*409600 + ixm[jx]*640;
            float tr = 0.f, ti = 0.f;
            #pragma unroll
            for (int jy = 0; jy < 6; jy++) {
                float2 v = __ldg(&g_buf[rowb + iym[jy]]);
                tr += ayr[jy]*v.x - ayi[jy]*v.y;
                ti += ayr[jy]*v.y + ayi[jy]*v.x;
            }
            accr += axr[jx]*tr - axi[jx]*ti;   // Re of (ax * t)
        }
        out[b*512000 + p] = accr;
    }
}

// ---------------- host launcher ----------------
extern "C" void kernel_launch(void* const* d_in, const int* in_sizes, int n_in,
                              void* d_out, int out_size) {
    const float *kr = 0, *ki = 0, *tkx = 0, *tky = 0;
    for (int i = 0; i < n_in; i++) {
        int s = in_sizes[i];
        if (s == 819200) {
            if (!kr) kr = (const float*)d_in[i];
            else if (!ki) ki = (const float*)d_in[i];
        } else if (s == 512000) {
            if (!tkx) tkx = (const float*)d_in[i];
            else if (!tky) tky = (const float*)d_in[i];
        }
    }
    if ((!kr || !ki || !tkx || !tky) && n_in >= 4) {
        kr  = (const float*)d_in[0];
        ki  = (const float*)d_in[1];
        tkx = (const float*)d_in[2];
        tky = (const float*)d_in[3];
    }
    if (!kr || !ki || !tkx || !tky || !d_out) return;
    float* out = (float*)d_out;

    k_init<<<1, 640>>>();
    k_ifft320_a<<<dim3(320, 8), 160>>>(kr, ki);          // IFFT along v
    k_trans320<<<dim3(10, 10, 8), dim3(32, 8)>>>();
    k_ifft320_b<<<dim3(320, 8), 160>>>();                // IFFT along u -> P^T
    k_reduce<<<dim3(25, 8), 256>>>();
    k_fin<<<1, 32>>>();
    k_fft640_a<<<dim3(320, 8), 320>>>();                 // FFT along x (normalized+apodized corner)
    k_trans640<<<dim3(20, 10, 8), dim3(32, 8)>>>();
    k_fft640_b<<<dim3(640, 8), 320>>>();                 // FFT along y -> Xos
    k_gather<<<2000, 256>>>(tkx, tky, out);
}

// round 11
// speedup vs baseline: 1.0727x; 1.0437x over previous
#include <cuda_runtime.h>
#include <math.h>

// ---------------- single consolidated static scratch ----------------
#define OFF_A 0
#define OFF_B 819200
#define OFF_C 1638400
#define OFF_D 3276800
#define OFF_X 4915200
#define NBUF  8192000

__device__ float2 g_buf[NBUF];
__device__ float4 g_part[200];
__device__ float4 g_norm[8];
__device__ float  g_apinv[320];
__device__ float2 g_tw[640];     // W640^m = (cos(2pi m/640), -sin(2pi m/640))  [forward]

// ---------------- init: twiddle table + apodization inverse ----------------
__global__ void k_init() {
    int t = threadIdx.x;
    if (t < 640) {
        double a = 2.0 * 3.141592653589793 * (double)t / 640.0;
        double c, s; sincos(a, &s, &c);
        g_tw[t] = make_float2((float)c, (float)(-s));
    }
    if (t < 320) {
        double beta = 3.141592653589793 * sqrt(19.45);
        double f = (t - 160.0) / 640.0;
        double w6f = 3.141592653589793 * 6.0 * f;
        double arg = beta*beta - w6f*w6f;
        double z = sqrt(arg);
        double a = sinh(z) / z;
        double a0 = sinh(beta) / beta;
        g_apinv[t] = (float)(a0 / a);
    }
}

// ---------------- complex helpers ----------------
template<bool CONJ>
__device__ __forceinline__ float2 cmulw(float2 v, float2 w) {
    float wy = CONJ ? -w.y : w.y;
    return make_float2(v.x*w.x - v.y*wy, v.x*wy + v.y*w.x);
}

// radix-4 DIT butterfly in shared memory; inputs pre-twiddled by w1,w2,w3
template<bool CONJ>
__device__ __forceinline__ void r4(float2* s, int base, int L,
                                   float2 w1, float2 w2, float2 w3) {
    float2 t0 = s[base];
    float2 t1 = cmulw<CONJ>(s[base+L],   w1);
    float2 t2 = cmulw<CONJ>(s[base+2*L], w2);
    float2 t3 = cmulw<CONJ>(s[base+3*L], w3);
    float e0r=t0.x+t2.x, e0i=t0.y+t2.y;
    float e1r=t0.x-t2.x, e1i=t0.y-t2.y;
    float o0r=t1.x+t3.x, o0i=t1.y+t3.y;
    float o1r=t1.x-t3.x, o1i=t1.y-t3.y;
    s[base]     = make_float2(e0r+o0r, e0i+o0i);
    s[base+2*L] = make_float2(e0r-o0r, e0i-o0i);
    if (!CONJ) {
        s[base+L]   = make_float2(e1r+o1i, e1i-o1r);
        s[base+3*L] = make_float2(e1r-o1i, e1i+o1r);
    } else {
        s[base+L]   = make_float2(e1r-o1i, e1i+o1r);
        s[base+3*L] = make_float2(e1r+o1i, e1i-o1r);
    }
}

// base-4 digit reversal of 3 digits (values 0..63)
__device__ __forceinline__ int drev4(int j) {
    return ((j & 3) << 4) | (j & 12) | (j >> 4);
}

// 320-point FFT stages: srow = this row's sh base (320 float2), rt in [0,80)
// Input must be loaded as srow[g*64 + j] = x[g + 5*drev4(j)]. 3 radix-4 stages + radix-5.
template<bool CONJ>
__device__ __forceinline__ void fft320_stages(float2* srow, int rt, int obase) {
    int g = rt >> 4, bf = rt & 15;
    float2* s = srow + g*64;
    __syncthreads();                        // after caller's load
    // stage 0: L=1 (twiddles = 1)
    r4<CONJ>(s, bf*4, 1, g_tw[0], g_tw[0], g_tw[0]);
    __syncthreads();
    // stage 1: L=4
    {
        int j = bf & 3, base = (bf >> 2)*16 + j;
        r4<CONJ>(s, base, 4, g_tw[j*40], g_tw[j*80], g_tw[j*120]);
    }
    __syncthreads();
    // stage 2: L=16
    r4<CONJ>(s, bf, 16, g_tw[bf*10], g_tw[bf*20], g_tw[bf*30]);
    __syncthreads();
    // radix-5 combine (j = rt < 64), twiddle W320^{n1 j} = W640^{2 n1 j}
    if (rt < 64) {
        float2 z[5];
        z[0] = srow[rt];
        #pragma unroll
        for (int n1 = 1; n1 < 5; n1++)
            z[n1] = cmulw<CONJ>(srow[n1*64 + rt], g_tw[2*n1*rt]);
        const float W5R[5] = {1.f, 0.309016994374947f, -0.809016994374947f, -0.809016994374947f, 0.309016994374947f};
        const float W5I[5] = {0.f, 0.951056516295154f, 0.587785252292473f, -0.587785252292473f, -0.951056516295154f};
        const float s5 = CONJ ? 1.f : -1.f;
        #pragma unroll
        for (int k1 = 0; k1 < 5; k1++) {
            float ar = z[0].x, ai = z[0].y;
            #pragma unroll
            for (int n1 = 1; n1 < 5; n1++) {
                int q = (n1 * k1) % 5;
                float wr = W5R[q], wi = s5 * W5I[q];
                ar += wr*z[n1].x - wi*z[n1].y;
                ai += wr*z[n1].y + wi*z[n1].x;
            }
            g_buf[obase + rt + 64*k1] = make_float2(ar, ai);
        }
    }
}

// 640-point forward FFT stages (input: caller stored srow[g*128+2k]=srow[g*128+2k+1]=x[g+5*drev4(k)],
// exploiting zero upper half -> stage0 radix-2 is pure duplication). rt in [0,160).
__device__ __forceinline__ void fft640_stages(float2* srow, int rt, int obase) {
    int g = rt >> 5, bf = rt & 31;
    float2* s = srow + g*128;
    __syncthreads();                        // after caller's load
    // stage 1: L=2
    {
        int j = bf & 1, base = (bf >> 1)*8 + j;
        r4<false>(s, base, 2, g_tw[j*80], g_tw[j*160], g_tw[j*240]);
    }
    __syncthreads();
    // stage 2: L=8
    {
        int j = bf & 7, base = (bf >> 3)*32 + j;
        r4<false>(s, base, 8, g_tw[j*20], g_tw[j*40], g_tw[j*60]);
    }
    __syncthreads();
    // stage 3: L=32
    r4<false>(s, bf, 32, g_tw[bf*5], g_tw[bf*10], g_tw[bf*15]);
    __syncthreads();
    // radix-5 (j = rt < 128), twiddle W640^{n1 j}
    if (rt < 128) {
        float2 z[5];
        z[0] = srow[rt];
        #pragma unroll
        for (int n1 = 1; n1 < 5; n1++)
            z[n1] = cmulw<false>(srow[n1*128 + rt], g_tw[n1*rt]);
        const float W5R[5] = {1.f, 0.309016994374947f, -0.809016994374947f, -0.809016994374947f, 0.309016994374947f};
        const float W5I[5] = {0.f, 0.951056516295154f, 0.587785252292473f, -0.587785252292473f, -0.951056516295154f};
        #pragma unroll
        for (int k1 = 0; k1 < 5; k1++) {
            float ar = z[0].x, ai = z[0].y;
            #pragma unroll
            for (int n1 = 1; n1 < 5; n1++) {
                int q = (n1 * k1) % 5;
                float wr = W5R[q], wi = -W5I[q];
                ar += wr*z[n1].x - wi*z[n1].y;
                ai += wr*z[n1].y + wi*z[n1].x;
            }
            g_buf[obase + rt + 128*k1] = make_float2(ar, ai);
        }
    }
}

// ---------------- phase 1: 320-point inverse FFTs (2 rows per block) ----------------
__global__ __launch_bounds__(160) void k_ifft320_a(const float* __restrict__ kr,
                                                   const float* __restrict__ ki) {
    __shared__ float2 sh[2][320];
    int r = threadIdx.x / 80, rt = threadIdx.x % 80;
    int b = blockIdx.y, u = blockIdx.x*2 + r;
    int rowbase = (b*320 + u)*320;
    #pragma unroll
    for (int i = 0; i < 4; i++) {
        int e = rt + 80*i;
        int g = e >> 6, j = e & 63;
        int src = rowbase + g + 5*drev4(j);
        sh[r][e] = make_float2(__ldg(&kr[src]), __ldg(&ki[src]));
    }
    fft320_stages<true>(sh[r], rt, OFF_A + rowbase);
}

__global__ __launch_bounds__(160) void k_ifft320_b() {
    __shared__ float2 sh[2][320];
    int r = threadIdx.x / 80, rt = threadIdx.x % 80;
    int b = blockIdx.y, y = blockIdx.x*2 + r;
    int rowbase = (b*320 + y)*320;
    #pragma unroll
    for (int i = 0; i < 4; i++) {
        int e = rt + 80*i;
        int g = e >> 6, j = e & 63;
        sh[r][e] = g_buf[OFF_B + rowbase + g + 5*drev4(j)];
    }
    fft320_stages<true>(sh[r], rt, OFF_A + rowbase);
}

// ---------------- transposes ----------------
__global__ void k_trans320() {
    __shared__ float2 tile[32][33];
    int b = blockIdx.z;
    int base = b*320*320;
    int c = blockIdx.x*32 + threadIdx.x;
    int r0 = blockIdx.y*32;
    #pragma unroll
    for (int i = threadIdx.y; i < 32; i += 8)
        tile[i][threadIdx.x] = g_buf[OFF_A + base + (r0 + i)*320 + c];
    __syncthreads();
    int oc = r0 + threadIdx.x;
    int or0 = blockIdx.x*32;
    #pragma unroll
    for (int i = threadIdx.y; i < 32; i += 8)
        g_buf[OFF_B + base + (or0 + i)*320 + oc] = tile[threadIdx.x][i];
}

__global__ void k_trans640() {
    __shared__ float2 tile[32][33];
    int b = blockIdx.z;
    int c = blockIdx.x*32 + threadIdx.x;
    int r0 = blockIdx.y*32;
    #pragma unroll
    for (int i = threadIdx.y; i < 32; i += 8)
        tile[i][threadIdx.x] = g_buf[OFF_C + b*320*640 + (r0 + i)*640 + c];
    __syncthreads();
    int oc = r0 + threadIdx.x;
    int or0 = blockIdx.x*32;
    #pragma unroll
    for (int i = threadIdx.y; i < 32; i += 8)
        g_buf[OFF_D + b*640*320 + (or0 + i)*320 + oc] = tile[threadIdx.x][i];
}

// ---------------- two-stage reduction for mean/std ----------------
__global__ __launch_bounds__(256) void k_reduce() {
    __shared__ float4 warpsum[8];
    int b = blockIdx.y;
    float sR = 0.f, sR2 = 0.f, sI = 0.f, sI2 = 0.f;
    int base = blockIdx.x*4096;
    #pragma unroll
    for (int i = 0; i < 16; i++) {
        int idx = base + threadIdx.x + i*256;
        float2 v = g_buf[OFF_A + b*102400 + idx];
        int y = idx / 320;
        int x = idx - y*320;
        float sg = ((x + y) & 1) ? -1.f : 1.f;
        sR  += sg * v.x;
        sR2 += v.x * v.x;
        sI  += sg * v.y;
        sI2 += v.y * v.y;
    }
    #pragma unroll
    for (int o = 16; o > 0; o >>= 1) {
        sR  += __shfl_down_sync(0xffffffff, sR,  o);
        sR2 += __shfl_down_sync(0xffffffff, sR2, o);
        sI  += __shfl_down_sync(0xffffffff, sI,  o);
        sI2 += __shfl_down_sync(0xffffffff, sI2, o);
    }
    int lane = threadIdx.x & 31, wid = threadIdx.x >> 5;
    if (lane == 0) warpsum[wid] = make_float4(sR, sR2, sI, sI2);
    __syncthreads();
    if (threadIdx.x == 0) {
        float4 t = warpsum[0];
        #pragma unroll
        for (int w = 1; w < 8; w++) {
            float4 u = warpsum[w];
            t.x += u.x; t.y += u.y; t.z += u.z; t.w += u.w;
        }
        g_part[b*25 + blockIdx.x] = t;
    }
}

__global__ void k_fin() {
    int b = threadIdx.x;
    if (b >= 8) return;
    double sR = 0, sR2 = 0, sI = 0, sI2 = 0;
    for (int j = 0; j < 25; j++) {
        float4 t = g_part[b*25 + j];
        sR += t.x; sR2 += t.y; sI += t.z; sI2 += t.w;
    }
    const double N = 102400.0;
    double sv_r = sR / 320.0;
    double sq_r = sR2 / 102400.0;
    double sv_i = sI / 320.0;
    double sq_i = sI2 / 102400.0;
    double mR = sv_r / N;
    double vR = (sq_r - sv_r*sv_r/N) / (N - 1.0);
    double mI = sv_i / N;
    double vI = (sq_i - sv_i*sv_i/N) / (N - 1.0);
    g_norm[b] = make_float4((float)mR, (float)(1.0/sqrt(vR)),
                            (float)mI, (float)(1.0/sqrt(vI)));
}

// ---------------- phase 2: 640-point forward FFTs (2 rows per block) ----------------
__global__ __launch_bounds__(320) void k_fft640_a() {
    __shared__ float2 sh[2][640];
    int r = threadIdx.x / 160, rt = threadIdx.x % 160;
    int b = blockIdx.y, y = blockIdx.x*2 + r;
    float4 nm = g_norm[b];
    int yy = (y < 160) ? y + 160 : y - 160;
    float apy = g_apinv[y];
    #pragma unroll
    for (int i = 0; i < 2; i++) {
        int pk = rt + 160*i;               // pair index 0..319
        int g = pk >> 6, k = pk & 63;
        int x = g + 5*drev4(k);            // always < 320
        int xx = (x < 160) ? x + 160 : x - 160;
        float2 p = g_buf[OFF_A + (b*320 + yy)*320 + xx];
        float c = ((x + y) & 1) ? -0.003125f : 0.003125f;   // s(x,y)/320
        float re = (c*p.x - nm.x) * nm.y;
        float im = (c*p.y - nm.z) * nm.w;
        float sc = apy * g_apinv[x];
        float2 v = make_float2(re*sc, im*sc);
        sh[r][g*128 + 2*k]     = v;        // fused trivial radix-2 (upper half zero)
        sh[r][g*128 + 2*k + 1] = v;
    }
    fft640_stages(sh[r], rt, OFF_C + (b*320 + y)*640);
}

__global__ __launch_bounds__(320) void k_fft640_b() {
    __shared__ float2 sh[2][640];
    int r = threadIdx.x / 160, rt = threadIdx.x % 160;
    int b = blockIdx.y, u = blockIdx.x*2 + r;
    #pragma unroll
    for (int i = 0; i < 2; i++) {
        int pk = rt + 160*i;
        int g = pk >> 6, k = pk & 63;
        int src = g + 5*drev4(k);          // always < 320
        float2 v = g_buf[OFF_D + b*640*320 + u*320 + src];
        sh[r][g*128 + 2*k]     = v;
        sh[r][g*128 + 2*k + 1] = v;
    }
    fft640_stages(sh[r], rt, OFF_X + (b*640 + u)*640);
}

// ---------------- Kaiser-Bessel i0 (fast exp) and gather ----------------
__device__ __forceinline__ float i0f(float x) {
    if (x < 3.75f) {
        float t = x * (1.0f/3.75f); float t2 = t*t;
        return 1.0f + t2*(3.5156229f + t2*(3.0899424f + t2*(1.2067492f +
               t2*(0.2659732f + t2*(0.0360768f + t2*0.0045813f)))));
    } else {
        float t = 3.75f / x;
        float p = 0.39894228f + t*(0.01328592f + t*(0.00225319f + t*(-0.00157565f +
                  t*(0.00916281f + t*(-0.02057706f + t*(0.02635537f +
                  t*(-0.01647633f + t*0.00392377f)))))));
        return __expf(x) * rsqrtf(x) * p;
    }
}

__global__ __launch_bounds__(256) void k_gather(const float* __restrict__ tkx,
                                                const float* __restrict__ tky,
                                                float* __restrict__ out) {
    int p = blockIdx.x*256 + threadIdx.x;
    if (p >= 512000) return;
    const float beta = (float)(3.141592653589793 * sqrt(19.45));
    const float inv_i0b = 1.0f / i0f(beta);
    float gx = __ldg(&tkx[p]) * 2.0f;
    float gy = __ldg(&tky[p]) * 2.0f;
    if (!(gx > -321.f && gx < 321.f)) gx = 0.f;
    if (!(gy > -321.f && gy < 321.f)) gy = 0.f;
    int ix0 = (int)floorf(gx) - 2;
    int iy0 = (int)floorf(gy) - 2;
    float axr[6], axi[6], ayr[6], ayi[6];
    int ixm[6], iym[6];
    #pragma unroll
    for (int j = 0; j < 6; j++) {
        {
            float d = gx - (float)(ix0 + j);
            float arg = fmaxf(1.0f - d*d*(1.0f/9.0f), 0.0f);
            float w = i0f(beta * sqrtf(arg)) * inv_i0b;
            int q = (ix0 + j + 1024) & 3;
            axr[j] = (q == 0) ? w : ((q == 2) ? -w : 0.f);
            axi[j] = (q == 1) ? w : ((q == 3) ? -w : 0.f);
            int v = ix0 + j; if (v < 0) v += 640;
            ixm[j] = v;
        }
        {
            float d = gy - (float)(iy0 + j);
            float arg = fmaxf(1.0f - d*d*(1.0f/9.0f), 0.0f);
            float w = i0f(beta * sqrtf(arg)) * inv_i0b;
            int q = (iy0 + j + 1024) & 3;
            ayr[j] = (q == 0) ? w : ((q == 2) ? -w : 0.f);
            ayi[j] = (q == 1) ? w : ((q == 3) ? -w : 0.f);
            int v = iy0 + j; if (v < 0) v += 640;
            iym[j] = v;
        }
    }
    #pragma unroll 1
    for (int b = 0; b < 8; b++) {
        float accr = 0.f;
        #pragma unroll
        for (int jx = 0; jx < 6; jx++) {
            int rowb = OFF_X + b*409600 + ixm[jx]*640;
            float tr = 0.f, ti = 0.f;
            #pragma unroll
            for (int jy = 0; jy < 6; jy++) {
                float2 v = __ldg(&g_buf[rowb + iym[jy]]);
                tr += ayr[jy]*v.x - ayi[jy]*v.y;
                ti += ayr[jy]*v.y + ayi[jy]*v.x;
            }
            accr += axr[jx]*tr - axi[jx]*ti;
        }
        out[b*512000 + p] = accr;
    }
}

// ---------------- host launcher ----------------
extern "C" void kernel_launch(void* const* d_in, const int* in_sizes, int n_in,
                              void* d_out, int out_size) {
    const float *kr = 0, *ki = 0, *tkx = 0, *tky = 0;
    for (int i = 0; i < n_in; i++) {
        int s = in_sizes[i];
        if (s == 819200) {
            if (!kr) kr = (const float*)d_in[i];
            else if (!ki) ki = (const float*)d_in[i];
        } else if (s == 512000) {
            if (!tkx) tkx = (const float*)d_in[i];
            else if (!tky) tky = (const float*)d_in[i];
        }
    }
    if ((!kr || !ki || !tkx || !tky) && n_in >= 4) {
        kr  = (const float*)d_in[0];
        ki  = (const float*)d_in[1];
        tkx = (const float*)d_in[2];
        tky = (const float*)d_in[3];
    }
    if (!kr || !ki || !tkx || !tky || !d_out) return;
    float* out = (float*)d_out;

    k_init<<<1, 640>>>();
    k_ifft320_a<<<dim3(160, 8), 160>>>(kr, ki);          // IFFT along v
    k_trans320<<<dim3(10, 10, 8), dim3(32, 8)>>>();
    k_ifft320_b<<<dim3(160, 8), 160>>>();                // IFFT along u -> P^T
    k_reduce<<<dim3(25, 8), 256>>>();
    k_fin<<<1, 32>>>();
    k_fft640_a<<<dim3(160, 8), 320>>>();                 // FFT along x (normalized+apodized corner)
    k_trans640<<<dim3(20, 10, 8), dim3(32, 8)>>>();
    k_fft640_b<<<dim3(320, 8), 320>>>();                 // FFT along y -> Xos
    k_gather<<<2000, 256>>>(tkx, tky, out);
}